// round 3
// baseline (speedup 1.0000x reference)
#include <cuda_runtime.h>
#include <cstdint>

#define N_NODES 50000
#define D 96
#define D4 (D/4)          // 24 float4 per row
#define TILE_ROWS 24
#define TX 24             // 24 col-groups of 4 -> 96 cols
#define TY 8              // 8 * 3 rows -> 24 rows per tile
#define RPT 3             // rows per thread

// ---- device scratch (static allocation: allowed) ----
__device__ float g_deg_out[N_NODES];
__device__ float g_deg_in[N_NODES];
__device__ float g_h[(size_t)N_NODES * D];   // h_scaled = (x@W) * inv_sqrt(deg_out)

// ---- kernel 1: zero output (poisoned 0xAA) and degree counters ----
__global__ void k_init(float4* __restrict__ out) {
    int i = blockIdx.x * blockDim.x + threadIdx.x;
    const int total4 = N_NODES * D4;
    if (i < total4) out[i] = make_float4(0.f, 0.f, 0.f, 0.f);
    if (i < N_NODES) { g_deg_out[i] = 0.f; g_deg_in[i] = 0.f; }
}

// ---- kernel 2: degree counts ----
__global__ void k_deg(const int* __restrict__ src,
                      const int* __restrict__ dst, int E) {
    int e = blockIdx.x * blockDim.x + threadIdx.x;
    if (e < E) {
        atomicAdd(&g_deg_out[src[e]], 1.0f);
        atomicAdd(&g_deg_in[dst[e]], 1.0f);
    }
}

// ---- kernel 3: h_scaled = (x @ W) * inv_sqrt(deg_out) ----
__global__ __launch_bounds__(TX * TY)
void k_gemm(const float* __restrict__ x, const float* __restrict__ Wg) {
    __shared__ float Ws[D * D];          // 36864 B
    __shared__ float xs[TILE_ROWS * D];  //  9216 B   (total 46080 B < 48K)

    const int tid = threadIdx.y * TX + threadIdx.x;
    const int nth = TX * TY;

    // stage W [96x96] row-major: Ws[k*96 + j] = W[k][j]
    for (int i = tid; i < D * D / 4; i += nth)
        ((float4*)Ws)[i] = ((const float4*)Wg)[i];

    const int rbase = blockIdx.x * TILE_ROWS;

    // stage x tile (zero-pad rows past N)
    for (int i = tid; i < TILE_ROWS * D4; i += nth) {
        int r = i / D4, c = i % D4;
        int g = rbase + r;
        float4 v = make_float4(0.f, 0.f, 0.f, 0.f);
        if (g < N_NODES) v = ((const float4*)(x + (size_t)g * D))[c];
        ((float4*)xs)[r * D4 + c] = v;
    }
    __syncthreads();

    float4 acc[RPT];
    #pragma unroll
    for (int r = 0; r < RPT; r++) acc[r] = make_float4(0.f, 0.f, 0.f, 0.f);

    const int tx4 = threadIdx.x * 4;
    const int ry  = threadIdx.y * RPT;

    #pragma unroll
    for (int k = 0; k < D; k += 4) {
        float4 w0 = *(const float4*)&Ws[(k + 0) * D + tx4];
        float4 w1 = *(const float4*)&Ws[(k + 1) * D + tx4];
        float4 w2 = *(const float4*)&Ws[(k + 2) * D + tx4];
        float4 w3 = *(const float4*)&Ws[(k + 3) * D + tx4];
        #pragma unroll
        for (int r = 0; r < RPT; r++) {
            float4 xv = *(const float4*)&xs[(ry + r) * D + k];
            acc[r].x += xv.x * w0.x + xv.y * w1.x + xv.z * w2.x + xv.w * w3.x;
            acc[r].y += xv.x * w0.y + xv.y * w1.y + xv.z * w2.y + xv.w * w3.y;
            acc[r].z += xv.x * w0.z + xv.y * w1.z + xv.z * w2.z + xv.w * w3.z;
            acc[r].w += xv.x * w0.w + xv.y * w1.w + xv.z * w2.w + xv.w * w3.w;
        }
    }

    #pragma unroll
    for (int r = 0; r < RPT; r++) {
        int row = rbase + ry + r;
        if (row < N_NODES) {
            float dg  = g_deg_out[row];
            float inv = dg > 0.f ? rsqrtf(dg) : 0.f;
            float4 o = make_float4(acc[r].x * inv, acc[r].y * inv,
                                   acc[r].z * inv, acc[r].w * inv);
            *(float4*)&g_h[(size_t)row * D + tx4] = o;
        }
    }
}

// ---- kernel 4: edge scatter with vectorized global reduction ----
// one thread per (edge, float4-chunk): 24 chunks per edge
__global__ void k_scatter(const int* __restrict__ src,
                          const int* __restrict__ dst,
                          float* __restrict__ out, int E) {
    int idx = blockIdx.x * blockDim.x + threadIdx.x;  // < E*24 = 19.2M, fits int
    int e = idx / D4;
    int v = idx - e * D4;
    if (e >= E) return;
    int s = __ldg(&src[e]);
    int d = __ldg(&dst[e]);
    float4 val = __ldg((const float4*)(g_h + (size_t)s * D) + v);
    float* addr = out + (size_t)d * D + v * 4;
    asm volatile("red.global.add.v4.f32 [%0], {%1, %2, %3, %4};"
                 :: "l"(addr), "f"(val.x), "f"(val.y), "f"(val.z), "f"(val.w)
                 : "memory");
}

// ---- kernel 5: out = out * inv_sqrt(deg_in) + b ----
__global__ void k_final(float4* __restrict__ out, const float* __restrict__ b) {
    int i = blockIdx.x * blockDim.x + threadIdx.x;
    const int total4 = N_NODES * D4;
    if (i >= total4) return;
    int node = i / D4;
    int c    = i - node * D4;
    float dg  = g_deg_in[node];
    float inv = dg > 0.f ? rsqrtf(dg) : 0.f;
    float4 o  = out[i];
    float4 bb = ((const float4*)b)[c];
    o.x = o.x * inv + bb.x;
    o.y = o.y * inv + bb.y;
    o.z = o.z * inv + bb.z;
    o.w = o.w * inv + bb.w;
    out[i] = o;
}

extern "C" void kernel_launch(void* const* d_in, const int* in_sizes, int n_in,
                              void* d_out, int out_size) {
    const float* x   = (const float*)d_in[0];      // [N, 96]
    const float* W   = (const float*)d_in[1];      // [96, 96]
    const float* b   = (const float*)d_in[2];      // [96]
    const int*   src = (const int*)d_in[3];        // [E] int32 (JAX x64 disabled)
    const int*   dst = (const int*)d_in[4];        // [E] int32
    float* out = (float*)d_out;                    // [N, 96]
    const int E = in_sizes[3];

    const int total4 = N_NODES * D4;  // 1.2M float4

    k_init<<<(total4 + 255) / 256, 256>>>((float4*)out);
    k_deg<<<(E + 255) / 256, 256>>>(src, dst, E);
    k_gemm<<<(N_NODES + TILE_ROWS - 1) / TILE_ROWS, dim3(TX, TY)>>>(x, W);

    long long scat_threads = (long long)E * D4;
    int scat_blocks = (int)((scat_threads + 255) / 256);
    k_scatter<<<scat_blocks, 256>>>(src, dst, out, E);

    k_final<<<(total4 + 255) / 256, 256>>>((float4*)out, b);
}

// round 4
// speedup vs baseline: 1.0061x; 1.0061x over previous
#include <cuda_runtime.h>
#include <cstdint>

#define N_NODES 50000
#define D 96
#define D4 (D/4)          // 24 float4 per row
#define TILE_ROWS 24
#define TX 24             // 24 col-groups of 4 -> 96 cols
#define TY 8              // 8 * 3 rows -> 24 rows per tile
#define RPT 3             // rows per thread

// ---- device scratch (static allocation: allowed) ----
__device__ float g_deg_out[N_NODES];
__device__ float g_deg_in[N_NODES];
__device__ float g_h[(size_t)N_NODES * D];   // h_scaled = (x@W) * inv_sqrt(deg_out)

// ---- kernel 1: zero output (poisoned 0xAA) and degree counters ----
__global__ void k_init(float4* __restrict__ out) {
    int i = blockIdx.x * blockDim.x + threadIdx.x;
    const int total4 = N_NODES * D4;
    if (i < total4) out[i] = make_float4(0.f, 0.f, 0.f, 0.f);
    if (i < N_NODES) { g_deg_out[i] = 0.f; g_deg_in[i] = 0.f; }
}

// ---- kernel 2: degree counts ----
__global__ void k_deg(const int* __restrict__ src,
                      const int* __restrict__ dst, int E) {
    int e = blockIdx.x * blockDim.x + threadIdx.x;
    if (e < E) {
        atomicAdd(&g_deg_out[src[e]], 1.0f);
        atomicAdd(&g_deg_in[dst[e]], 1.0f);
    }
}

// ---- kernel 3: h_scaled = (x @ W) * inv_sqrt(deg_out) ----
__global__ __launch_bounds__(TX * TY)
void k_gemm(const float* __restrict__ x, const float* __restrict__ Wg) {
    __shared__ float Ws[D * D];          // 36864 B
    __shared__ float xs[TILE_ROWS * D];  //  9216 B   (total 46080 B < 48K)

    const int tid = threadIdx.y * TX + threadIdx.x;
    const int nth = TX * TY;

    // stage W [96x96] row-major: Ws[k*96 + j] = W[k][j]
    for (int i = tid; i < D * D / 4; i += nth)
        ((float4*)Ws)[i] = ((const float4*)Wg)[i];

    const int rbase = blockIdx.x * TILE_ROWS;

    // stage x tile (zero-pad rows past N)
    for (int i = tid; i < TILE_ROWS * D4; i += nth) {
        int r = i / D4, c = i % D4;
        int g = rbase + r;
        float4 v = make_float4(0.f, 0.f, 0.f, 0.f);
        if (g < N_NODES) v = ((const float4*)(x + (size_t)g * D))[c];
        ((float4*)xs)[r * D4 + c] = v;
    }
    __syncthreads();

    float4 acc[RPT];
    #pragma unroll
    for (int r = 0; r < RPT; r++) acc[r] = make_float4(0.f, 0.f, 0.f, 0.f);

    const int tx4 = threadIdx.x * 4;
    const int ry  = threadIdx.y * RPT;

    #pragma unroll
    for (int k = 0; k < D; k += 4) {
        float4 w0 = *(const float4*)&Ws[(k + 0) * D + tx4];
        float4 w1 = *(const float4*)&Ws[(k + 1) * D + tx4];
        float4 w2 = *(const float4*)&Ws[(k + 2) * D + tx4];
        float4 w3 = *(const float4*)&Ws[(k + 3) * D + tx4];
        #pragma unroll
        for (int r = 0; r < RPT; r++) {
            float4 xv = *(const float4*)&xs[(ry + r) * D + k];
            acc[r].x += xv.x * w0.x + xv.y * w1.x + xv.z * w2.x + xv.w * w3.x;
            acc[r].y += xv.x * w0.y + xv.y * w1.y + xv.z * w2.y + xv.w * w3.y;
            acc[r].z += xv.x * w0.z + xv.y * w1.z + xv.z * w2.z + xv.w * w3.z;
            acc[r].w += xv.x * w0.w + xv.y * w1.w + xv.z * w2.w + xv.w * w3.w;
        }
    }

    #pragma unroll
    for (int r = 0; r < RPT; r++) {
        int row = rbase + ry + r;
        if (row < N_NODES) {
            float dg  = g_deg_out[row];
            float inv = dg > 0.f ? rsqrtf(dg) : 0.f;
            float4 o = make_float4(acc[r].x * inv, acc[r].y * inv,
                                   acc[r].z * inv, acc[r].w * inv);
            *(float4*)&g_h[(size_t)row * D + tx4] = o;
        }
    }
}

// ---- kernel 4: edge scatter with vectorized global reduction ----
// one thread per (edge, float4-chunk): 24 chunks per edge
__global__ void k_scatter(const int* __restrict__ src,
                          const int* __restrict__ dst,
                          float* __restrict__ out, int E) {
    int idx = blockIdx.x * blockDim.x + threadIdx.x;  // < E*24 = 19.2M, fits int
    int e = idx / D4;
    int v = idx - e * D4;
    if (e >= E) return;
    int s = __ldg(&src[e]);
    int d = __ldg(&dst[e]);
    float4 val = __ldg((const float4*)(g_h + (size_t)s * D) + v);
    float* addr = out + (size_t)d * D + v * 4;
    asm volatile("red.global.add.v4.f32 [%0], {%1, %2, %3, %4};"
                 :: "l"(addr), "f"(val.x), "f"(val.y), "f"(val.z), "f"(val.w)
                 : "memory");
}

// ---- kernel 5: out = out * inv_sqrt(deg_in) + b ----
__global__ void k_final(float4* __restrict__ out, const float* __restrict__ b) {
    int i = blockIdx.x * blockDim.x + threadIdx.x;
    const int total4 = N_NODES * D4;
    if (i >= total4) return;
    int node = i / D4;
    int c    = i - node * D4;
    float dg  = g_deg_in[node];
    float inv = dg > 0.f ? rsqrtf(dg) : 0.f;
    float4 o  = out[i];
    float4 bb = ((const float4*)b)[c];
    o.x = o.x * inv + bb.x;
    o.y = o.y * inv + bb.y;
    o.z = o.z * inv + bb.z;
    o.w = o.w * inv + bb.w;
    out[i] = o;
}

extern "C" void kernel_launch(void* const* d_in, const int* in_sizes, int n_in,
                              void* d_out, int out_size) {
    const float* x   = (const float*)d_in[0];      // [N, 96]
    const float* W   = (const float*)d_in[1];      // [96, 96]
    const float* b   = (const float*)d_in[2];      // [96]
    const int*   src = (const int*)d_in[3];        // [E] int32 (JAX x64 disabled)
    const int*   dst = (const int*)d_in[4];        // [E] int32
    float* out = (float*)d_out;                    // [N, 96]
    const int E = in_sizes[3];

    const int total4 = N_NODES * D4;  // 1.2M float4

    k_init<<<(total4 + 255) / 256, 256>>>((float4*)out);
    k_deg<<<(E + 255) / 256, 256>>>(src, dst, E);
    k_gemm<<<(N_NODES + TILE_ROWS - 1) / TILE_ROWS, dim3(TX, TY)>>>(x, W);

    long long scat_threads = (long long)E * D4;
    int scat_blocks = (int)((scat_threads + 255) / 256);
    k_scatter<<<scat_blocks, 256>>>(src, dst, out, E);

    k_final<<<(total4 + 255) / 256, 256>>>((float4*)out, b);
}

// round 5
// speedup vs baseline: 1.3180x; 1.3101x over previous
#include <cuda_runtime.h>
#include <cstdint>

#define N_NODES 50000
#define MAX_E   800000
#define D 96
#define D4 (D/4)
#define TILE_ROWS 24
#define TX 24
#define TY 8
#define RPT 3
#define NBLK ((N_NODES + 255) / 256)   // 196 scan blocks

// ---- device scratch ----
__device__ int   g_deg_out_i[N_NODES];
__device__ int   g_deg_in_i[N_NODES];
__device__ int   g_row_ptr[N_NODES + 1];
__device__ int   g_fill[N_NODES];
__device__ int   g_bsum[256];
__device__ int   g_csr_src[MAX_E];
__device__ float g_h[(size_t)N_NODES * D];   // (x@W) * inv_sqrt(deg_out)

// ---- kernel: zero degree counters ----
__global__ void k_init() {
    int i = blockIdx.x * blockDim.x + threadIdx.x;
    if (i < N_NODES) { g_deg_out_i[i] = 0; g_deg_in_i[i] = 0; }
}

// ---- kernel: degree counts ----
__global__ void k_deg(const int* __restrict__ src,
                      const int* __restrict__ dst, int E) {
    int e = blockIdx.x * blockDim.x + threadIdx.x;
    if (e < E) {
        atomicAdd(&g_deg_out_i[src[e]], 1);
        atomicAdd(&g_deg_in_i[dst[e]], 1);
    }
}

// ---- scan step 1: per-block exclusive scan of deg_in ----
__global__ void k_scan1() {
    __shared__ int sh[256];
    int i = blockIdx.x * 256 + threadIdx.x;
    int v = (i < N_NODES) ? g_deg_in_i[i] : 0;
    sh[threadIdx.x] = v;
    __syncthreads();
    #pragma unroll
    for (int off = 1; off < 256; off <<= 1) {
        int t = (threadIdx.x >= off) ? sh[threadIdx.x - off] : 0;
        __syncthreads();
        sh[threadIdx.x] += t;
        __syncthreads();
    }
    if (i < N_NODES) g_row_ptr[i] = sh[threadIdx.x] - v;   // exclusive (local)
    if (threadIdx.x == 255) g_bsum[blockIdx.x] = sh[255];
}

// ---- scan step 2: exclusive scan of the 196 block sums (1 block) ----
__global__ void k_scan2() {
    __shared__ int sh[256];
    int v = (threadIdx.x < NBLK) ? g_bsum[threadIdx.x] : 0;
    sh[threadIdx.x] = v;
    __syncthreads();
    #pragma unroll
    for (int off = 1; off < 256; off <<= 1) {
        int t = (threadIdx.x >= off) ? sh[threadIdx.x - off] : 0;
        __syncthreads();
        sh[threadIdx.x] += t;
        __syncthreads();
    }
    if (threadIdx.x < NBLK) g_bsum[threadIdx.x] = sh[threadIdx.x] - v;
}

// ---- scan step 3: add block offsets, init fill cursors ----
__global__ void k_scan3(int E) {
    int i = blockIdx.x * 256 + threadIdx.x;
    if (i < N_NODES) {
        int p = g_row_ptr[i] + g_bsum[blockIdx.x];
        g_row_ptr[i] = p;
        g_fill[i] = p;
    }
    if (i == 0) g_row_ptr[N_NODES] = E;
}

// ---- kernel: bucket edges by dst ----
__global__ void k_fill(const int* __restrict__ src,
                       const int* __restrict__ dst, int E) {
    int e = blockIdx.x * blockDim.x + threadIdx.x;
    if (e < E) {
        int d = dst[e];
        int pos = atomicAdd(&g_fill[d], 1);
        g_csr_src[pos] = src[e];
    }
}

// ---- kernel: h_scaled = (x @ W) * inv_sqrt(deg_out) ----
__global__ __launch_bounds__(TX * TY)
void k_gemm(const float* __restrict__ x, const float* __restrict__ Wg) {
    __shared__ float Ws[D * D];          // 36864 B
    __shared__ float xs[TILE_ROWS * D];  //  9216 B

    const int tid = threadIdx.y * TX + threadIdx.x;
    const int nth = TX * TY;

    for (int i = tid; i < D * D / 4; i += nth)
        ((float4*)Ws)[i] = ((const float4*)Wg)[i];

    const int rbase = blockIdx.x * TILE_ROWS;

    for (int i = tid; i < TILE_ROWS * D4; i += nth) {
        int r = i / D4, c = i % D4;
        int g = rbase + r;
        float4 v = make_float4(0.f, 0.f, 0.f, 0.f);
        if (g < N_NODES) v = ((const float4*)(x + (size_t)g * D))[c];
        ((float4*)xs)[r * D4 + c] = v;
    }
    __syncthreads();

    float4 acc[RPT];
    #pragma unroll
    for (int r = 0; r < RPT; r++) acc[r] = make_float4(0.f, 0.f, 0.f, 0.f);

    const int tx4 = threadIdx.x * 4;
    const int ry  = threadIdx.y * RPT;

    #pragma unroll
    for (int k = 0; k < D; k += 4) {
        float4 w0 = *(const float4*)&Ws[(k + 0) * D + tx4];
        float4 w1 = *(const float4*)&Ws[(k + 1) * D + tx4];
        float4 w2 = *(const float4*)&Ws[(k + 2) * D + tx4];
        float4 w3 = *(const float4*)&Ws[(k + 3) * D + tx4];
        #pragma unroll
        for (int r = 0; r < RPT; r++) {
            float4 xv = *(const float4*)&xs[(ry + r) * D + k];
            acc[r].x += xv.x * w0.x + xv.y * w1.x + xv.z * w2.x + xv.w * w3.x;
            acc[r].y += xv.x * w0.y + xv.y * w1.y + xv.z * w2.y + xv.w * w3.y;
            acc[r].z += xv.x * w0.z + xv.y * w1.z + xv.z * w2.z + xv.w * w3.z;
            acc[r].w += xv.x * w0.w + xv.y * w1.w + xv.z * w2.w + xv.w * w3.w;
        }
    }

    #pragma unroll
    for (int r = 0; r < RPT; r++) {
        int row = rbase + ry + r;
        if (row < N_NODES) {
            float dg  = (float)g_deg_out_i[row];
            float inv = dg > 0.f ? rsqrtf(dg) : 0.f;
            float4 o = make_float4(acc[r].x * inv, acc[r].y * inv,
                                   acc[r].z * inv, acc[r].w * inv);
            *(float4*)&g_h[(size_t)row * D + tx4] = o;
        }
    }
}

// ---- kernel: aggregate per dst node (one warp per node, no atomics) ----
__global__ __launch_bounds__(256)
void k_agg(const float* __restrict__ b, float* __restrict__ out) {
    int warp = (blockIdx.x * blockDim.x + threadIdx.x) >> 5;
    int lane = threadIdx.x & 31;
    if (warp >= N_NODES) return;

    int beg = g_row_ptr[warp];
    int end = g_row_ptr[warp + 1];

    float a0 = 0.f, a1 = 0.f, a2 = 0.f;

    int j = beg;
    // 2-edge unrolled: 6 independent loads in flight
    for (; j + 1 < end; j += 2) {
        int s0 = __ldg(&g_csr_src[j]);
        int s1 = __ldg(&g_csr_src[j + 1]);
        const float* h0 = g_h + (size_t)s0 * D;
        const float* h1 = g_h + (size_t)s1 * D;
        float v00 = __ldg(h0 + lane);
        float v01 = __ldg(h0 + lane + 32);
        float v02 = __ldg(h0 + lane + 64);
        float v10 = __ldg(h1 + lane);
        float v11 = __ldg(h1 + lane + 32);
        float v12 = __ldg(h1 + lane + 64);
        a0 += v00 + v10;
        a1 += v01 + v11;
        a2 += v02 + v12;
    }
    if (j < end) {
        int s = __ldg(&g_csr_src[j]);
        const float* hp = g_h + (size_t)s * D;
        a0 += __ldg(hp + lane);
        a1 += __ldg(hp + lane + 32);
        a2 += __ldg(hp + lane + 64);
    }

    float dg  = (float)g_deg_in_i[warp];
    float inv = dg > 0.f ? rsqrtf(dg) : 0.f;

    float* op = out + (size_t)warp * D;
    op[lane]      = a0 * inv + b[lane];
    op[lane + 32] = a1 * inv + b[lane + 32];
    op[lane + 64] = a2 * inv + b[lane + 64];
}

extern "C" void kernel_launch(void* const* d_in, const int* in_sizes, int n_in,
                              void* d_out, int out_size) {
    const float* x   = (const float*)d_in[0];
    const float* W   = (const float*)d_in[1];
    const float* b   = (const float*)d_in[2];
    const int*   src = (const int*)d_in[3];
    const int*   dst = (const int*)d_in[4];
    float* out = (float*)d_out;
    const int E = in_sizes[3];

    k_init<<<(N_NODES + 255) / 256, 256>>>();
    k_deg<<<(E + 255) / 256, 256>>>(src, dst, E);
    k_scan1<<<NBLK, 256>>>();
    k_scan2<<<1, 256>>>();
    k_scan3<<<NBLK, 256>>>(E);
    k_fill<<<(E + 255) / 256, 256>>>(src, dst, E);
    k_gemm<<<(N_NODES + TILE_ROWS - 1) / TILE_ROWS, dim3(TX, TY)>>>(x, W);

    long long agg_threads = (long long)N_NODES * 32;
    k_agg<<<(int)((agg_threads + 255) / 256), 256>>>(b, out);
}